// round 3
// baseline (speedup 1.0000x reference)
#include <cuda_runtime.h>

#define NN 50000
#define EE 800000
#define INF 128
#define HD  128
#define NEG 0.2f
#define LOG2E 1.44269504088896340736f

#define BM 128
#define BK 32
#define NTILE ((NN + BM - 1) / BM)    // 391
#define HBLK 148                       // histogram blocks
#define SBLK 148                       // scatter blocks
#define GEMM0 HBLK
#define NGEMM (3 * NTILE)
#define SCANB (GEMM0 + NGEMM)          // scan block index
#define SCAT0 (SCANB + 1)
#define GRID1 (SCAT0 + SBLK)

#define AST 132                        // As row stride (floats)
#define WRS 260                        // Wr row stride (floats, replicated pairs)
#define SMEM_BYTES ((BK * AST + BK * WRS) * 4)

// ---------------- scratch ------------------------------------------------------
__device__ float g_fsrc[(size_t)NN * HD];   // pre-scaled by LOG2E
__device__ float g_fdst[(size_t)NN * HD];   // pre-scaled by LOG2E
__device__ float g_fv  [(size_t)NN * HD];
__device__ int   g_deg [NN];                // zeroed by scan pass each launch
__device__ int   g_offs[NN + 1];
__device__ int   g_cur [NN];
__device__ int   g_ssrc[EE];
__device__ int   g_histdone;                // reset by scan block each launch
__device__ int   g_scandone;                // reset by aggregate each launch

#define FFMA2(d, a, b) asm("fma.rn.f32x2 %0, %1, %2, %0;" : "+l"(d) : "l"(a), "l"(b))

__device__ __forceinline__ float ex2f(float x) {
    float r;
    asm("ex2.approx.f32 %0, %1;" : "=f"(r) : "f"(x));
    return r;
}

// ---------------- mega-kernel: GEMM + hist + scan + scatter --------------------
__global__ void __launch_bounds__(256, 2)
gemm_csr_kernel(const float* __restrict__ feat,
                const float* __restrict__ Wsrc, const float* __restrict__ bsrc,
                const float* __restrict__ Wdst, const float* __restrict__ bdst,
                const float* __restrict__ Wv,   const float* __restrict__ bv,
                const int* __restrict__ src, const int* __restrict__ dst)
{
    const int bid = blockIdx.x;
    const int tid = threadIdx.x;

    // ---------- role: histogram (first wave) ----------
    if (bid < HBLK) {
        for (int i = bid * 256 + tid; i < EE; i += HBLK * 256)
            atomicAdd(&g_deg[dst[i]], 1);
        __threadfence();
        __syncthreads();
        if (tid == 0) atomicAdd(&g_histdone, 1);
        return;
    }

    // ---------- role: scan (single block; spins until hist done) ----------
    if (bid == SCANB) {
        if (tid == 0) {
            while (atomicAdd(&g_histdone, 0) < HBLK) __nanosleep(128);
            atomicExch(&g_histdone, 0);   // reset for next replay
        }
        __syncthreads();
        __threadfence();

        const int CH = (NN + 255) / 256;          // 196
        const int beg = tid * CH;
        const int end = (beg + CH < NN) ? beg + CH : NN;

        // pass A: per-thread chunk sum
        int s = 0;
#pragma unroll 4
        for (int i = beg; i < end; i++) s += __ldcg(&g_deg[i]);

        // block exclusive scan of 256 sums
        __shared__ int wsum[8];
        const int lane = tid & 31, wid = tid >> 5;
        int inc = s;
#pragma unroll
        for (int o = 1; o < 32; o <<= 1) {
            const int u = __shfl_up_sync(0xffffffffu, inc, o);
            if (lane >= o) inc += u;
        }
        if (lane == 31) wsum[wid] = inc;
        __syncthreads();
        if (wid == 0 && lane < 8) {
            int w = wsum[lane];
#pragma unroll
            for (int o = 1; o < 8; o <<= 1) {
                const int u = __shfl_up_sync(0x000000ffu, w, o);
                if (lane >= o) w += u;
            }
            wsum[lane] = w;
        }
        __syncthreads();
        int run = (inc - s) + (wid ? wsum[wid - 1] : 0);

        // pass B: write offsets, reset degrees
#pragma unroll 4
        for (int i = beg; i < end; i++) {
            const int d = __ldcg(&g_deg[i]);
            __stcg(&g_deg[i], 0);
            g_offs[i] = run;
            g_cur[i]  = run;
            run += d;
        }
        if (tid == 255) g_offs[NN] = run;

        __threadfence();
        __syncthreads();
        if (tid == 0) atomicExch(&g_scandone, 1);
        return;
    }

    // ---------- role: scatter (spins until scan done) ----------
    if (bid >= SCAT0) {
        if (tid == 0)
            while (atomicAdd(&g_scandone, 0) == 0) __nanosleep(128);
        __syncthreads();
        for (int i = (bid - SCAT0) * 256 + tid; i < EE; i += SBLK * 256) {
            const int d = dst[i];
            const int p = atomicAdd(&g_cur[d], 1);
            g_ssrc[p] = src[i];
        }
        return;
    }

    // ---------- role: GEMM ----------
    extern __shared__ float sm[];
    float* As = sm;                  // [BK][AST]   a, natural order
    float* Wr = sm + BK * AST;       // [BK][WRS]   w, each value duplicated

    const int bx   = bid - GEMM0;
    const int mat  = bx / NTILE;
    const int tile = bx % NTILE;

    const float* W;
    const float* b;
    float* Out;
    float scale;
    if (mat == 0)      { W = Wsrc; b = bsrc; Out = g_fsrc; scale = LOG2E; }
    else if (mat == 1) { W = Wdst; b = bdst; Out = g_fdst; scale = LOG2E; }
    else               { W = Wv;   b = bv;   Out = g_fv;   scale = 1.0f; }

    const int tx  = tid & 31;     // n0 = tx*4
    const int ty  = tid >> 5;     // m0 = ty*16 (8 pairs)
    const int m0g = tile * BM;

    unsigned long long acc[8][4];   // [m-pair][n]: lo=m even, hi=m odd
#pragma unroll
    for (int p = 0; p < 8; p++)
#pragma unroll
        for (int n = 0; n < 4; n++) acc[p][n] = 0ULL;

    for (int kc = 0; kc < INF / BK; kc++) {
        const int k0 = kc * BK;

        // feat tile -> As[kk][m]
#pragma unroll
        for (int t = tid; t < BM * BK / 4; t += 256) {
            const int r = t >> 3, c = t & 7;
            const int row = m0g + r;
            float4 v = make_float4(0.f, 0.f, 0.f, 0.f);
            if (row < NN) v = *(const float4*)(feat + (size_t)row * INF + k0 + c * 4);
            As[(c * 4 + 0) * AST + r] = v.x;
            As[(c * 4 + 1) * AST + r] = v.y;
            As[(c * 4 + 2) * AST + r] = v.z;
            As[(c * 4 + 3) * AST + r] = v.w;
        }
        // W tile -> Wr[kk][2j] = Wr[kk][2j+1] = W[j][kk]
#pragma unroll
        for (int t = tid; t < HD * BK / 4; t += 256) {
            const int j = t >> 3, c = t & 7;
            const float4 w4 = *(const float4*)(W + (size_t)j * INF + k0 + c * 4);
            float* p0 = Wr + (c * 4 + 0) * WRS + 2 * j; p0[0] = w4.x; p0[1] = w4.x;
            float* p1 = Wr + (c * 4 + 1) * WRS + 2 * j; p1[0] = w4.y; p1[1] = w4.y;
            float* p2 = Wr + (c * 4 + 2) * WRS + 2 * j; p2[0] = w4.z; p2[1] = w4.z;
            float* p3 = Wr + (c * 4 + 3) * WRS + 2 * j; p3[0] = w4.w; p3[1] = w4.w;
        }
        __syncthreads();

#pragma unroll
        for (int kk = 0; kk < BK; kk++) {
            const float* ab = As + kk * AST + ty * 16;
            const float* wb = Wr + kk * WRS + tx * 8;
            const ulonglong2 a01 = *(const ulonglong2*)(ab);
            const ulonglong2 a23 = *(const ulonglong2*)(ab + 4);
            const ulonglong2 a45 = *(const ulonglong2*)(ab + 8);
            const ulonglong2 a67 = *(const ulonglong2*)(ab + 12);
            const ulonglong2 w01 = *(const ulonglong2*)(wb);      // {w0,w0},{w1,w1}
            const ulonglong2 w23 = *(const ulonglong2*)(wb + 4);  // {w2,w2},{w3,w3}
#pragma unroll
            for (int n = 0; n < 4; n++) {
                const unsigned long long wv = (n == 0) ? w01.x : (n == 1) ? w01.y
                                            : (n == 2) ? w23.x : w23.y;
                FFMA2(acc[0][n], a01.x, wv);
                FFMA2(acc[1][n], a01.y, wv);
                FFMA2(acc[2][n], a23.x, wv);
                FFMA2(acc[3][n], a23.y, wv);
                FFMA2(acc[4][n], a45.x, wv);
                FFMA2(acc[5][n], a45.y, wv);
                FFMA2(acc[6][n], a67.x, wv);
                FFMA2(acc[7][n], a67.y, wv);
            }
        }
        __syncthreads();
    }

    const float4 bb = *(const float4*)(b + tx * 4);
#pragma unroll
    for (int p = 0; p < 8; p++) {
        const int row0 = m0g + ty * 16 + 2 * p;
        const float2 f0 = *(const float2*)&acc[p][0];
        const float2 f1 = *(const float2*)&acc[p][1];
        const float2 f2 = *(const float2*)&acc[p][2];
        const float2 f3 = *(const float2*)&acc[p][3];
        if (row0 < NN) {
            float4 o;
            o.x = (f0.x + bb.x) * scale;
            o.y = (f1.x + bb.y) * scale;
            o.z = (f2.x + bb.z) * scale;
            o.w = (f3.x + bb.w) * scale;
            *(float4*)(Out + (size_t)row0 * HD + tx * 4) = o;
        }
        if (row0 + 1 < NN) {
            float4 o;
            o.x = (f0.y + bb.x) * scale;
            o.y = (f1.y + bb.y) * scale;
            o.z = (f2.y + bb.z) * scale;
            o.w = (f3.y + bb.w) * scale;
            *(float4*)(Out + (size_t)(row0 + 1) * HD + tx * 4) = o;
        }
    }
}

// ---------------- aggregation: one warp per dst node --------------------------
__global__ void aggregate_kernel(float* __restrict__ out)
{
    if (blockIdx.x == 0 && threadIdx.x == 0) atomicExch(&g_scandone, 0);

    const int warp = (blockIdx.x * blockDim.x + threadIdx.x) >> 5;
    if (warp >= NN) return;
    const int lane = threadIdx.x & 31;
    const int n = warp;

    const int beg = g_offs[n];
    const int end = g_offs[n + 1];

    const size_t fo = (size_t)n * HD + lane * 4;
    const float4 fd = *(const float4*)(g_fdst + fo);

    float nx = 0.f, ny = 0.f, nz = 0.f, nw = 0.f;
    float dx = 0.f, dy = 0.f, dz = 0.f, dw = 0.f;

#define EDGE_STEP(fs, fvv)                                                        \
    do {                                                                          \
        float a_, e_;                                                             \
        a_ = fs.x + fd.x; e_ = ex2f(fmaxf(a_, NEG * a_)); dx += e_; nx = fmaf(fvv.x, e_, nx); \
        a_ = fs.y + fd.y; e_ = ex2f(fmaxf(a_, NEG * a_)); dy += e_; ny = fmaf(fvv.y, e_, ny); \
        a_ = fs.z + fd.z; e_ = ex2f(fmaxf(a_, NEG * a_)); dz += e_; nz = fmaf(fvv.z, e_, nz); \
        a_ = fs.w + fd.w; e_ = ex2f(fmaxf(a_, NEG * a_)); dw += e_; nw = fmaf(fvv.w, e_, nw); \
    } while (0)

    for (int base = beg; base < end; base += 32) {
        const int rem = end - base;
        const int m = rem < 32 ? rem : 32;
        const int s_l = (lane < m) ? __ldg(&g_ssrc[base + lane]) : 0;
        int t = 0;
        for (; t + 2 <= m; t += 2) {
            const int s0 = __shfl_sync(0xffffffffu, s_l, t);
            const int s1 = __shfl_sync(0xffffffffu, s_l, t + 1);
            const size_t o0 = (size_t)s0 * HD + lane * 4;
            const size_t o1 = (size_t)s1 * HD + lane * 4;
            const float4 fs0 = *(const float4*)(g_fsrc + o0);
            const float4 fv0 = *(const float4*)(g_fv + o0);
            const float4 fs1 = *(const float4*)(g_fsrc + o1);
            const float4 fv1 = *(const float4*)(g_fv + o1);
            EDGE_STEP(fs0, fv0);
            EDGE_STEP(fs1, fv1);
        }
        if (t < m) {
            const int s0 = __shfl_sync(0xffffffffu, s_l, t);
            const size_t o0 = (size_t)s0 * HD + lane * 4;
            const float4 fs0 = *(const float4*)(g_fsrc + o0);
            const float4 fv0 = *(const float4*)(g_fv + o0);
            EDGE_STEP(fs0, fv0);
        }
    }

    float4 o;
    o.x = dx > 0.f ? nx / dx : 0.f;
    o.y = dy > 0.f ? ny / dy : 0.f;
    o.z = dz > 0.f ? nz / dz : 0.f;
    o.w = dw > 0.f ? nw / dw : 0.f;
    *(float4*)(out + fo) = o;
}

// ---------------- launch -------------------------------------------------------
extern "C" void kernel_launch(void* const* d_in, const int* in_sizes, int n_in,
                              void* d_out, int out_size)
{
    const float* feat = (const float*)d_in[0];
    const float* Wsrc = (const float*)d_in[1];
    const float* bsrc = (const float*)d_in[2];
    const float* Wdst = (const float*)d_in[3];
    const float* bdst = (const float*)d_in[4];
    const float* Wv   = (const float*)d_in[5];
    const float* bv   = (const float*)d_in[6];
    const int*   src  = (const int*)d_in[7];
    const int*   dst  = (const int*)d_in[8];
    float* out = (float*)d_out;

    cudaFuncSetAttribute(gemm_csr_kernel,
                         cudaFuncAttributeMaxDynamicSharedMemorySize, SMEM_BYTES);

    gemm_csr_kernel<<<GRID1, 256, SMEM_BYTES>>>(
        feat, Wsrc, bsrc, Wdst, bdst, Wv, bv, src, dst);

    aggregate_kernel<<<(NN * 32 + 255) / 256, 256>>>(out);
}

// round 4
// speedup vs baseline: 1.3103x; 1.3103x over previous
#include <cuda_runtime.h>

#define NN 50000
#define EE 800000
#define INF 128
#define HD  128
#define NEG 0.2f
#define LOG2E 1.44269504088896340736f

#define BM 128
#define BK 32
#define NTILE ((NN + BM - 1) / BM)    // 391
#define HBLK 148
#define ASP 130                        // pair stride per k-row (pad vs bank conflicts)
#define WTS 132                        // float stride per k-row
#define SMEM_BYTES ((BK * ASP * 2 + BK * WTS) * 4)

// ---------------- scratch ------------------------------------------------------
__device__ float g_fsrc[(size_t)NN * HD];   // pre-scaled by LOG2E
__device__ float g_fdst[(size_t)NN * HD];   // pre-scaled by LOG2E
__device__ float g_fv  [(size_t)NN * HD];
__device__ int   g_deg [NN];          // zero-initialized; re-zeroed by scan_kernel
__device__ int   g_offs[NN + 1];
__device__ int   g_cur [NN];
__device__ int   g_ssrc[EE];

#define FFMA2(d, a, b) asm("fma.rn.f32x2 %0, %1, %2, %0;" : "+l"(d) : "l"(a), "l"(b))

__device__ __forceinline__ float ex2f(float x) {
    float r;
    asm("ex2.approx.f32 %0, %1;" : "=f"(r) : "f"(x));
    return r;
}

// ---------------- fused projection GEMM (f32x2) + dst histogram ----------------
// Round-2 structure (known good): accumulators paired over n; a replicated
// {a,a} in smem (warp-broadcast reads), w plain (16B-stride LDS.128,
// conflict-free). Blocks < HBLK do the degree histogram, overlapping the
// FMA-bound GEMM waves.
__global__ void __launch_bounds__(256, 2)
gemm_hist_kernel(const float* __restrict__ feat,
                 const float* __restrict__ Wsrc, const float* __restrict__ bsrc,
                 const float* __restrict__ Wdst, const float* __restrict__ bdst,
                 const float* __restrict__ Wv,   const float* __restrict__ bv,
                 const int* __restrict__ dst)
{
    if (blockIdx.x < HBLK) {
        for (int i = blockIdx.x * 256 + threadIdx.x; i < EE; i += HBLK * 256)
            atomicAdd(&g_deg[dst[i]], 1);
        return;
    }

    extern __shared__ float sm[];
    float* As2 = sm;                    // BK rows of ASP pairs ({a,a} float2)
    float* Wt  = sm + BK * ASP * 2;     // BK rows of WTS floats

    const int bx   = blockIdx.x - HBLK;
    const int mat  = bx / NTILE;
    const int tile = bx % NTILE;

    const float* W;
    const float* b;
    float* Out;
    float scale;
    if (mat == 0)      { W = Wsrc; b = bsrc; Out = g_fsrc; scale = LOG2E; }
    else if (mat == 1) { W = Wdst; b = bdst; Out = g_fdst; scale = LOG2E; }
    else               { W = Wv;   b = bv;   Out = g_fv;   scale = 1.0f; }

    const int tid = threadIdx.x;
    const int tx  = tid & 31;     // n0 = tx*4
    const int ty  = tid >> 5;     // m0 = ty*16
    const int m0g = tile * BM;

    unsigned long long acc[16][2];
#pragma unroll
    for (int m = 0; m < 16; m++) { acc[m][0] = 0ULL; acc[m][1] = 0ULL; }

    for (int kc = 0; kc < INF / BK; kc++) {
        const int k0 = kc * BK;

        // feat tile -> As2[kk][m] replicated pairs
#pragma unroll
        for (int t = tid; t < BM * BK / 4; t += 256) {
            const int r = t >> 3, c = t & 7;
            const int row = m0g + r;
            float4 v = make_float4(0.f, 0.f, 0.f, 0.f);
            if (row < NN) v = *(const float4*)(feat + (size_t)row * INF + k0 + c * 4);
            float* p;
            p = As2 + ((c * 4 + 0) * ASP + r) * 2; p[0] = v.x; p[1] = v.x;
            p = As2 + ((c * 4 + 1) * ASP + r) * 2; p[0] = v.y; p[1] = v.y;
            p = As2 + ((c * 4 + 2) * ASP + r) * 2; p[0] = v.z; p[1] = v.z;
            p = As2 + ((c * 4 + 3) * ASP + r) * 2; p[0] = v.w; p[1] = v.w;
        }
        // W tile -> Wt[kk][j]
#pragma unroll
        for (int t = tid; t < HD * BK / 4; t += 256) {
            const int j = t >> 3, c = t & 7;
            const float4 w4 = *(const float4*)(W + (size_t)j * INF + k0 + c * 4);
            Wt[(c * 4 + 0) * WTS + j] = w4.x;
            Wt[(c * 4 + 1) * WTS + j] = w4.y;
            Wt[(c * 4 + 2) * WTS + j] = w4.z;
            Wt[(c * 4 + 3) * WTS + j] = w4.w;
        }
        __syncthreads();

#pragma unroll 16
        for (int kk = 0; kk < BK; kk++) {
            const ulonglong2 wv = *(const ulonglong2*)(Wt + kk * WTS + tx * 4);
            const float* abase = As2 + (kk * ASP + ty * 16) * 2;
#pragma unroll
            for (int j = 0; j < 8; j++) {
                const ulonglong2 av = *(const ulonglong2*)(abase + j * 4);
                FFMA2(acc[2 * j + 0][0], av.x, wv.x);
                FFMA2(acc[2 * j + 0][1], av.x, wv.y);
                FFMA2(acc[2 * j + 1][0], av.y, wv.x);
                FFMA2(acc[2 * j + 1][1], av.y, wv.y);
            }
        }
        __syncthreads();
    }

    const float4 bb = *(const float4*)(b + tx * 4);
#pragma unroll
    for (int m = 0; m < 16; m++) {
        const int row = m0g + ty * 16 + m;
        if (row < NN) {
            const float2 lo = *(const float2*)&acc[m][0];
            const float2 hi = *(const float2*)&acc[m][1];
            float4 o;
            o.x = (lo.x + bb.x) * scale;
            o.y = (lo.y + bb.y) * scale;
            o.z = (hi.x + bb.z) * scale;
            o.w = (hi.y + bb.w) * scale;
            *(float4*)(Out + (size_t)row * HD + tx * 4) = o;
        }
    }
}

// ---------------- scan: coalesced tiled block scan; re-zeroes g_deg -----------
__global__ void scan_kernel()
{
    __shared__ int wsums[32];
    const int tid  = threadIdx.x;
    const int lane = tid & 31;
    const int wid  = tid >> 5;
    const int TILES = (NN + 1023) / 1024;

    int carry = 0;
    for (int t = 0; t < TILES; t++) {
        const int idx = t * 1024 + tid;
        int v = 0;
        if (idx < NN) { v = g_deg[idx]; g_deg[idx] = 0; }
        int s = v;
#pragma unroll
        for (int o = 1; o < 32; o <<= 1) {
            const int u = __shfl_up_sync(0xffffffffu, s, o);
            if (lane >= o) s += u;
        }
        if (lane == 31) wsums[wid] = s;
        __syncthreads();
        if (wid == 0) {
            int ws = wsums[lane];
#pragma unroll
            for (int o = 1; o < 32; o <<= 1) {
                const int u = __shfl_up_sync(0xffffffffu, ws, o);
                if (lane >= o) ws += u;
            }
            wsums[lane] = ws;
        }
        __syncthreads();
        const int excl = carry + (s - v) + (wid ? wsums[wid - 1] : 0);
        if (idx < NN) { g_offs[idx] = excl; g_cur[idx] = excl; }
        carry += wsums[31];
        __syncthreads();
    }
    if (tid == 0) g_offs[NN] = carry;
}

// ---------------- scatter ------------------------------------------------------
__global__ void scatter_kernel(const int* __restrict__ src, const int* __restrict__ dst)
{
    const int i = blockIdx.x * blockDim.x + threadIdx.x;
    if (i < EE) {
        const int d = dst[i];
        const int p = atomicAdd(&g_cur[d], 1);
        g_ssrc[p] = src[i];
    }
}

// ---------------- aggregation: one warp per dst node --------------------------
__global__ void aggregate_kernel(float* __restrict__ out)
{
    const int warp = (blockIdx.x * blockDim.x + threadIdx.x) >> 5;
    if (warp >= NN) return;
    const int lane = threadIdx.x & 31;
    const int n = warp;

    const int beg = g_offs[n];
    const int end = g_offs[n + 1];

    const size_t fo = (size_t)n * HD + lane * 4;
    const float4 fd = *(const float4*)(g_fdst + fo);

    float nx = 0.f, ny = 0.f, nz = 0.f, nw = 0.f;
    float dx = 0.f, dy = 0.f, dz = 0.f, dw = 0.f;

#define EDGE_STEP(fs, fvv)                                                        \
    do {                                                                          \
        float a_, e_;                                                             \
        a_ = fs.x + fd.x; e_ = ex2f(fmaxf(a_, NEG * a_)); dx += e_; nx = fmaf(fvv.x, e_, nx); \
        a_ = fs.y + fd.y; e_ = ex2f(fmaxf(a_, NEG * a_)); dy += e_; ny = fmaf(fvv.y, e_, ny); \
        a_ = fs.z + fd.z; e_ = ex2f(fmaxf(a_, NEG * a_)); dz += e_; nz = fmaf(fvv.z, e_, nz); \
        a_ = fs.w + fd.w; e_ = ex2f(fmaxf(a_, NEG * a_)); dw += e_; nw = fmaf(fvv.w, e_, nw); \
    } while (0)

    for (int base = beg; base < end; base += 32) {
        const int rem = end - base;
        const int m = rem < 32 ? rem : 32;
        const int s_l = (lane < m) ? __ldg(&g_ssrc[base + lane]) : 0;
        int t = 0;
        for (; t + 2 <= m; t += 2) {
            const int s0 = __shfl_sync(0xffffffffu, s_l, t);
            const int s1 = __shfl_sync(0xffffffffu, s_l, t + 1);
            const size_t o0 = (size_t)s0 * HD + lane * 4;
            const size_t o1 = (size_t)s1 * HD + lane * 4;
            const float4 fs0 = *(const float4*)(g_fsrc + o0);
            const float4 fv0 = *(const float4*)(g_fv + o0);
            const float4 fs1 = *(const float4*)(g_fsrc + o1);
            const float4 fv1 = *(const float4*)(g_fv + o1);
            EDGE_STEP(fs0, fv0);
            EDGE_STEP(fs1, fv1);
        }
        if (t < m) {
            const int s0 = __shfl_sync(0xffffffffu, s_l, t);
            const size_t o0 = (size_t)s0 * HD + lane * 4;
            const float4 fs0 = *(const float4*)(g_fsrc + o0);
            const float4 fv0 = *(const float4*)(g_fv + o0);
            EDGE_STEP(fs0, fv0);
        }
    }

    float4 o;
    o.x = dx > 0.f ? nx / dx : 0.f;
    o.y = dy > 0.f ? ny / dy : 0.f;
    o.z = dz > 0.f ? nz / dz : 0.f;
    o.w = dw > 0.f ? nw / dw : 0.f;
    *(float4*)(out + fo) = o;
}

// ---------------- launch -------------------------------------------------------
extern "C" void kernel_launch(void* const* d_in, const int* in_sizes, int n_in,
                              void* d_out, int out_size)
{
    const float* feat = (const float*)d_in[0];
    const float* Wsrc = (const float*)d_in[1];
    const float* bsrc = (const float*)d_in[2];
    const float* Wdst = (const float*)d_in[3];
    const float* bdst = (const float*)d_in[4];
    const float* Wv   = (const float*)d_in[5];
    const float* bv   = (const float*)d_in[6];
    const int*   src  = (const int*)d_in[7];
    const int*   dst  = (const int*)d_in[8];
    float* out = (float*)d_out;

    cudaFuncSetAttribute(gemm_hist_kernel,
                         cudaFuncAttributeMaxDynamicSharedMemorySize, SMEM_BYTES);

    gemm_hist_kernel<<<HBLK + 3 * NTILE, 256, SMEM_BYTES>>>(
        feat, Wsrc, bsrc, Wdst, bdst, Wv, bv, dst);

    scan_kernel<<<1, 1024>>>();
    scatter_kernel<<<(EE + 255) / 256, 256>>>(src, dst);
    aggregate_kernel<<<(NN * 32 + 255) / 256, 256>>>(out);
}

// round 5
// speedup vs baseline: 1.4230x; 1.0860x over previous
#include <cuda_runtime.h>

#define NN 50000
#define EE 800000
#define INF 128
#define HD  128
#define NEG 0.2f
#define LOG2E 1.44269504088896340736f

#define BM 128
#define BK 32
#define NTILE ((NN + BM - 1) / BM)    // 391
#define HBLK 148                       // histogram blocks (bids 0..147)
#define SCANB HBLK                     // scan block (bid 148)
#define SCAT0 (SCANB + 1)              // scatter blocks (bids 149..295)
#define SBLK 147
#define GEMM0 (SCAT0 + SBLK)           // 296
#define NGEMM (3 * NTILE)
#define GRID1 (GEMM0 + NGEMM)

#define ASP 130                        // pair stride per k-row (pad vs bank conflicts)
#define WTS 132                        // float stride per k-row
#define SMEM_BYTES ((BK * ASP * 2 + BK * WTS) * 4)

// ---------------- scratch ------------------------------------------------------
__device__ float g_fsv [(size_t)NN * 256];  // [node][0:128)=f_src*LOG2E, [128:256)=f_v
__device__ float g_fdst[(size_t)NN * HD];   // pre-scaled by LOG2E
__device__ int   g_deg [NN];                // zeroed by scan pass each launch
__device__ int   g_offs[NN + 1];
__device__ int   g_cur [NN];
__device__ int   g_ssrc[EE];
__device__ int   g_histdone;                // reset by scan block each launch
__device__ int   g_scandone;                // reset by aggregate each launch

#define FFMA2(d, a, b) asm("fma.rn.f32x2 %0, %1, %2, %0;" : "+l"(d) : "l"(a), "l"(b))

__device__ __forceinline__ float ex2f(float x) {
    float r;
    asm("ex2.approx.f32 %0, %1;" : "=f"(r) : "f"(x));
    return r;
}

// ---------------- mega-kernel: hist+scan+scatter (wave 1) + GEMM ---------------
// CSR roles occupy the FIRST 296 block ids so they are all resident in wave 1;
// the FMA-bound GEMM blocks stream in behind them and overlap the CSR chain.
// GEMM microkernel identical to the validated round-2/4 loop.
__global__ void __launch_bounds__(256, 2)
gemm_csr_kernel(const float* __restrict__ feat,
                const float* __restrict__ Wsrc, const float* __restrict__ bsrc,
                const float* __restrict__ Wdst, const float* __restrict__ bdst,
                const float* __restrict__ Wv,   const float* __restrict__ bv,
                const int* __restrict__ src, const int* __restrict__ dst)
{
    const int bid = blockIdx.x;
    const int tid = threadIdx.x;

    // ---------- role: histogram ----------
    if (bid < HBLK) {
        for (int i = bid * 256 + tid; i < EE; i += HBLK * 256)
            atomicAdd(&g_deg[dst[i]], 1);
        __threadfence();
        __syncthreads();
        if (tid == 0) atomicAdd(&g_histdone, 1);
        return;
    }

    // ---------- role: scan (single block; spins until hist done) ----------
    if (bid == SCANB) {
        if (tid == 0) {
            while (atomicAdd(&g_histdone, 0) < HBLK) __nanosleep(128);
            atomicExch(&g_histdone, 0);   // reset for next replay
        }
        __syncthreads();
        __threadfence();

        const int CH = (NN + 255) / 256;          // 196
        const int beg = tid * CH;
        const int end = (beg + CH < NN) ? beg + CH : NN;

        int s = 0;
#pragma unroll 4
        for (int i = beg; i < end; i++) s += __ldcg(&g_deg[i]);

        __shared__ int wsum[8];
        const int lane = tid & 31, wid = tid >> 5;
        int inc = s;
#pragma unroll
        for (int o = 1; o < 32; o <<= 1) {
            const int u = __shfl_up_sync(0xffffffffu, inc, o);
            if (lane >= o) inc += u;
        }
        if (lane == 31) wsum[wid] = inc;
        __syncthreads();
        if (wid == 0 && lane < 8) {
            int w = wsum[lane];
#pragma unroll
            for (int o = 1; o < 8; o <<= 1) {
                const int u = __shfl_up_sync(0x000000ffu, w, o);
                if (lane >= o) w += u;
            }
            wsum[lane] = w;
        }
        __syncthreads();
        int run = (inc - s) + (wid ? wsum[wid - 1] : 0);

#pragma unroll 4
        for (int i = beg; i < end; i++) {
            const int d = __ldcg(&g_deg[i]);
            __stcg(&g_deg[i], 0);
            g_offs[i] = run;
            g_cur[i]  = run;
            run += d;
        }
        if (tid == 255) g_offs[NN] = run;

        __threadfence();
        __syncthreads();
        if (tid == 0) atomicExch(&g_scandone, 1);
        return;
    }

    // ---------- role: scatter (spins until scan done) ----------
    if (bid < GEMM0) {
        if (tid == 0)
            while (atomicAdd(&g_scandone, 0) == 0) __nanosleep(128);
        __syncthreads();
        for (int i = (bid - SCAT0) * 256 + tid; i < EE; i += SBLK * 256) {
            const int d = dst[i];
            const int p = atomicAdd(&g_cur[d], 1);
            g_ssrc[p] = src[i];
        }
        return;
    }

    // ---------- role: GEMM (validated round-2/4 microkernel) ----------
    extern __shared__ float sm[];
    float* As2 = sm;                    // BK rows of ASP pairs ({a,a} float2)
    float* Wt  = sm + BK * ASP * 2;     // BK rows of WTS floats

    const int bx   = bid - GEMM0;
    const int mat  = bx / NTILE;
    const int tile = bx % NTILE;

    const float* W;
    const float* b;
    float* Out;
    float scale;
    unsigned rstride;
    if (mat == 0)      { W = Wsrc; b = bsrc; Out = g_fsv;       scale = LOG2E; rstride = 256; }
    else if (mat == 1) { W = Wdst; b = bdst; Out = g_fdst;      scale = LOG2E; rstride = 128; }
    else               { W = Wv;   b = bv;   Out = g_fsv + 128; scale = 1.0f;  rstride = 256; }

    const int tx  = tid & 31;     // n0 = tx*4
    const int ty  = tid >> 5;     // m0 = ty*16
    const int m0g = tile * BM;

    unsigned long long acc[16][2];
#pragma unroll
    for (int m = 0; m < 16; m++) { acc[m][0] = 0ULL; acc[m][1] = 0ULL; }

    for (int kc = 0; kc < INF / BK; kc++) {
        const int k0 = kc * BK;

#pragma unroll
        for (int t = tid; t < BM * BK / 4; t += 256) {
            const int r = t >> 3, c = t & 7;
            const int row = m0g + r;
            float4 v = make_float4(0.f, 0.f, 0.f, 0.f);
            if (row < NN) v = *(const float4*)(feat + (size_t)row * INF + k0 + c * 4);
            float* p;
            p = As2 + ((c * 4 + 0) * ASP + r) * 2; p[0] = v.x; p[1] = v.x;
            p = As2 + ((c * 4 + 1) * ASP + r) * 2; p[0] = v.y; p[1] = v.y;
            p = As2 + ((c * 4 + 2) * ASP + r) * 2; p[0] = v.z; p[1] = v.z;
            p = As2 + ((c * 4 + 3) * ASP + r) * 2; p[0] = v.w; p[1] = v.w;
        }
#pragma unroll
        for (int t = tid; t < HD * BK / 4; t += 256) {
            const int j = t >> 3, c = t & 7;
            const float4 w4 = *(const float4*)(W + (size_t)j * INF + k0 + c * 4);
            Wt[(c * 4 + 0) * WTS + j] = w4.x;
            Wt[(c * 4 + 1) * WTS + j] = w4.y;
            Wt[(c * 4 + 2) * WTS + j] = w4.z;
            Wt[(c * 4 + 3) * WTS + j] = w4.w;
        }
        __syncthreads();

#pragma unroll 16
        for (int kk = 0; kk < BK; kk++) {
            const ulonglong2 wv = *(const ulonglong2*)(Wt + kk * WTS + tx * 4);
            const float* abase = As2 + (kk * ASP + ty * 16) * 2;
#pragma unroll
            for (int j = 0; j < 8; j++) {
                const ulonglong2 av = *(const ulonglong2*)(abase + j * 4);
                FFMA2(acc[2 * j + 0][0], av.x, wv.x);
                FFMA2(acc[2 * j + 0][1], av.x, wv.y);
                FFMA2(acc[2 * j + 1][0], av.y, wv.x);
                FFMA2(acc[2 * j + 1][1], av.y, wv.y);
            }
        }
        __syncthreads();
    }

    const float4 bb = *(const float4*)(b + tx * 4);
#pragma unroll
    for (int m = 0; m < 16; m++) {
        const int row = m0g + ty * 16 + m;
        if (row < NN) {
            const float2 lo = *(const float2*)&acc[m][0];
            const float2 hi = *(const float2*)&acc[m][1];
            float4 o;
            o.x = (lo.x + bb.x) * scale;
            o.y = (lo.y + bb.y) * scale;
            o.z = (hi.x + bb.z) * scale;
            o.w = (hi.y + bb.w) * scale;
            *(float4*)(Out + (size_t)row * rstride + tx * 4) = o;
        }
    }
}

// ---------------- aggregation: one warp per dst node --------------------------
__global__ void aggregate_kernel(float* __restrict__ out)
{
    if (blockIdx.x == 0 && threadIdx.x == 0) atomicExch(&g_scandone, 0);

    const int warp = (blockIdx.x * blockDim.x + threadIdx.x) >> 5;
    if (warp >= NN) return;
    const int lane = threadIdx.x & 31;
    const unsigned lane4 = lane * 4;
    const int n = warp;

    const int beg = g_offs[n];
    const int end = g_offs[n + 1];

    const unsigned fo = ((unsigned)n << 7) + lane4;
    const float4 fd = *(const float4*)(g_fdst + fo);

    float nx = 0.f, ny = 0.f, nz = 0.f, nw = 0.f;
    float dx = 0.f, dy = 0.f, dz = 0.f, dw = 0.f;

#define EDGE_STEP(fs, fvv)                                                        \
    do {                                                                          \
        float a_, e_;                                                             \
        a_ = fs.x + fd.x; e_ = ex2f(fmaxf(a_, NEG * a_)); dx += e_; nx = fmaf(fvv.x, e_, nx); \
        a_ = fs.y + fd.y; e_ = ex2f(fmaxf(a_, NEG * a_)); dy += e_; ny = fmaf(fvv.y, e_, ny); \
        a_ = fs.z + fd.z; e_ = ex2f(fmaxf(a_, NEG * a_)); dz += e_; nz = fmaf(fvv.z, e_, nz); \
        a_ = fs.w + fd.w; e_ = ex2f(fmaxf(a_, NEG * a_)); dw += e_; nw = fmaf(fvv.w, e_, nw); \
    } while (0)

    for (int base = beg; base < end; base += 32) {
        const int rem = end - base;
        const int m = rem < 32 ? rem : 32;
        const int s_l = (lane < m) ? __ldg(&g_ssrc[base + lane]) : 0;
        int t = 0;
        for (; t + 2 <= m; t += 2) {
            const unsigned o0 = ((unsigned)__shfl_sync(0xffffffffu, s_l, t)     << 8) + lane4;
            const unsigned o1 = ((unsigned)__shfl_sync(0xffffffffu, s_l, t + 1) << 8) + lane4;
            const float4 fs0 = *(const float4*)(g_fsv + o0);
            const float4 fv0 = *(const float4*)(g_fsv + o0 + 128);
            const float4 fs1 = *(const float4*)(g_fsv + o1);
            const float4 fv1 = *(const float4*)(g_fsv + o1 + 128);
            EDGE_STEP(fs0, fv0);
            EDGE_STEP(fs1, fv1);
        }
        if (t < m) {
            const unsigned o0 = ((unsigned)__shfl_sync(0xffffffffu, s_l, t) << 8) + lane4;
            const float4 fs0 = *(const float4*)(g_fsv + o0);
            const float4 fv0 = *(const float4*)(g_fsv + o0 + 128);
            EDGE_STEP(fs0, fv0);
        }
    }

    float4 o;
    o.x = dx > 0.f ? nx / dx : 0.f;
    o.y = dy > 0.f ? ny / dy : 0.f;
    o.z = dz > 0.f ? nz / dz : 0.f;
    o.w = dw > 0.f ? nw / dw : 0.f;
    *(float4*)(out + fo) = o;
}

// ---------------- launch -------------------------------------------------------
extern "C" void kernel_launch(void* const* d_in, const int* in_sizes, int n_in,
                              void* d_out, int out_size)
{
    const float* feat = (const float*)d_in[0];
    const float* Wsrc = (const float*)d_in[1];
    const float* bsrc = (const float*)d_in[2];
    const float* Wdst = (const float*)d_in[3];
    const float* bdst = (const float*)d_in[4];
    const float* Wv   = (const float*)d_in[5];
    const float* bv   = (const float*)d_in[6];
    const int*   src  = (const int*)d_in[7];
    const int*   dst  = (const int*)d_in[8];
    float* out = (float*)d_out;

    cudaFuncSetAttribute(gemm_csr_kernel,
                         cudaFuncAttributeMaxDynamicSharedMemorySize, SMEM_BYTES);

    gemm_csr_kernel<<<GRID1, 256, SMEM_BYTES>>>(
        feat, Wsrc, bsrc, Wdst, bdst, Wv, bv, src, dst);

    aggregate_kernel<<<(NN * 32 + 255) / 256, 256>>>(out);
}

// round 6
// speedup vs baseline: 1.4327x; 1.0068x over previous
#include <cuda_runtime.h>

#define NN 50000
#define EE 800000
#define INF 128
#define HD  128
#define NEG 0.2f
#define LOG2E 1.44269504088896340736f

#define BM 128
#define BK 32
#define NTILE ((NN + BM - 1) / BM)    // 391
#define HBLK 148                       // histogram blocks (bids 0..147)
#define SCANB HBLK                     // scan block (bid 148)
#define SCAT0 (SCANB + 1)              // scatter blocks (bids 149..295)
#define SBLK 147
#define GEMM0 (SCAT0 + SBLK)           // 296
#define NGEMM (3 * NTILE)
#define GRID1 (GEMM0 + NGEMM)

#define AST 132                        // As row stride (floats), 16B-aligned rows
#define WTS 132                        // Wt row stride (floats)
#define SMEM_BYTES ((BK * AST + BK * WTS) * 4)

// ---------------- scratch ------------------------------------------------------
__device__ float g_fsv [(size_t)NN * 256];  // [node][0:128)=f_src*LOG2E, [128:256)=f_v
__device__ float g_fdst[(size_t)NN * HD];   // pre-scaled by LOG2E
__device__ int   g_deg [NN];                // zeroed by scan pass each launch
__device__ int   g_offs[NN + 1];
__device__ int   g_cur [NN];
__device__ int   g_ssrc[EE];
__device__ int   g_histdone;                // reset by scan block each launch
__device__ int   g_scandone;                // reset by aggregate each launch

#define FFMA2(d, a, b) asm("fma.rn.f32x2 %0, %1, %2, %0;" : "+l"(d) : "l"(a), "l"(b))
#define DUP2(d, s)     asm("mov.b64 %0, {%1,%1};" : "=l"(d) : "f"(s))

__device__ __forceinline__ float ex2f(float x) {
    float r;
    asm("ex2.approx.f32 %0, %1;" : "=f"(r) : "f"(x));
    return r;
}

// ---------------- mega-kernel: hist+scan+scatter (wave 1) + GEMM ---------------
// CSR roles occupy the FIRST 296 block ids (resident in wave 1); FMA-bound GEMM
// blocks stream in behind and overlap the CSR chain.
// GEMM inner loop: accumulators paired over m; a read as BROADCAST ulonglong2
// pairs from natural-layout smem (crossbar-free), w read conflict-free 16B-stride
// LDS.128 and duplicated into {w,w} via mov.b64. FFMA2-pipe-bound by design.
__global__ void __launch_bounds__(256, 2)
gemm_csr_kernel(const float* __restrict__ feat,
                const float* __restrict__ Wsrc, const float* __restrict__ bsrc,
                const float* __restrict__ Wdst, const float* __restrict__ bdst,
                const float* __restrict__ Wv,   const float* __restrict__ bv,
                const int* __restrict__ src, const int* __restrict__ dst)
{
    const int bid = blockIdx.x;
    const int tid = threadIdx.x;

    // ---------- role: histogram ----------
    if (bid < HBLK) {
        for (int i = bid * 256 + tid; i < EE; i += HBLK * 256)
            atomicAdd(&g_deg[dst[i]], 1);
        __threadfence();
        __syncthreads();
        if (tid == 0) atomicAdd(&g_histdone, 1);
        return;
    }

    // ---------- role: scan (single block; spins until hist done) ----------
    if (bid == SCANB) {
        if (tid == 0) {
            while (atomicAdd(&g_histdone, 0) < HBLK) __nanosleep(128);
            atomicExch(&g_histdone, 0);   // reset for next replay
        }
        __syncthreads();
        __threadfence();

        const int CH = (NN + 255) / 256;          // 196
        const int beg = tid * CH;
        const int end = (beg + CH < NN) ? beg + CH : NN;

        int s = 0;
#pragma unroll 4
        for (int i = beg; i < end; i++) s += __ldcg(&g_deg[i]);

        __shared__ int wsum[8];
        const int lane = tid & 31, wid = tid >> 5;
        int inc = s;
#pragma unroll
        for (int o = 1; o < 32; o <<= 1) {
            const int u = __shfl_up_sync(0xffffffffu, inc, o);
            if (lane >= o) inc += u;
        }
        if (lane == 31) wsum[wid] = inc;
        __syncthreads();
        if (wid == 0 && lane < 8) {
            int w = wsum[lane];
#pragma unroll
            for (int o = 1; o < 8; o <<= 1) {
                const int u = __shfl_up_sync(0x000000ffu, w, o);
                if (lane >= o) w += u;
            }
            wsum[lane] = w;
        }
        __syncthreads();
        int run = (inc - s) + (wid ? wsum[wid - 1] : 0);

#pragma unroll 4
        for (int i = beg; i < end; i++) {
            const int d = __ldcg(&g_deg[i]);
            __stcg(&g_deg[i], 0);
            g_offs[i] = run;
            g_cur[i]  = run;
            run += d;
        }
        if (tid == 255) g_offs[NN] = run;

        __threadfence();
        __syncthreads();
        if (tid == 0) atomicExch(&g_scandone, 1);
        return;
    }

    // ---------- role: scatter (spins until scan done) ----------
    if (bid < GEMM0) {
        if (tid == 0)
            while (atomicAdd(&g_scandone, 0) == 0) __nanosleep(128);
        __syncthreads();
        for (int i = (bid - SCAT0) * 256 + tid; i < EE; i += SBLK * 256) {
            const int d = dst[i];
            const int p = atomicAdd(&g_cur[d], 1);
            g_ssrc[p] = src[i];
        }
        return;
    }

    // ---------- role: GEMM ----------
    extern __shared__ float sm[];
    float* As = sm;                  // [BK][AST]  natural a layout (no replication)
    float* Wt = sm + BK * AST;       // [BK][WTS]  natural w layout

    const int bx   = bid - GEMM0;
    const int mat  = bx / NTILE;
    const int tile = bx % NTILE;

    const float* W;
    const float* b;
    float* Out;
    float scale;
    unsigned rstride;
    if (mat == 0)      { W = Wsrc; b = bsrc; Out = g_fsv;       scale = LOG2E; rstride = 256; }
    else if (mat == 1) { W = Wdst; b = bdst; Out = g_fdst;      scale = LOG2E; rstride = 128; }
    else               { W = Wv;   b = bv;   Out = g_fsv + 128; scale = 1.0f;  rstride = 256; }

    const int tx  = tid & 31;     // n0 = tx*4
    const int ty  = tid >> 5;     // m0 = ty*16 (warp-uniform)
    const int m0g = tile * BM;

    unsigned long long acc[8][4];   // [m-pair][n]: lo = m even, hi = m odd
#pragma unroll
    for (int p = 0; p < 8; p++)
#pragma unroll
        for (int n = 0; n < 4; n++) acc[p][n] = 0ULL;

    for (int kc = 0; kc < INF / BK; kc++) {
        const int k0 = kc * BK;

        // feat tile -> As[kk][m]
#pragma unroll
        for (int t = tid; t < BM * BK / 4; t += 256) {
            const int r = t >> 3, c = t & 7;
            const int row = m0g + r;
            float4 v = make_float4(0.f, 0.f, 0.f, 0.f);
            if (row < NN) v = *(const float4*)(feat + (size_t)row * INF + k0 + c * 4);
            As[(c * 4 + 0) * AST + r] = v.x;
            As[(c * 4 + 1) * AST + r] = v.y;
            As[(c * 4 + 2) * AST + r] = v.z;
            As[(c * 4 + 3) * AST + r] = v.w;
        }
        // W tile -> Wt[kk][j]
#pragma unroll
        for (int t = tid; t < HD * BK / 4; t += 256) {
            const int j = t >> 3, c = t & 7;
            const float4 w4 = *(const float4*)(W + (size_t)j * INF + k0 + c * 4);
            Wt[(c * 4 + 0) * WTS + j] = w4.x;
            Wt[(c * 4 + 1) * WTS + j] = w4.y;
            Wt[(c * 4 + 2) * WTS + j] = w4.z;
            Wt[(c * 4 + 3) * WTS + j] = w4.w;
        }
        __syncthreads();

#pragma unroll 8
        for (int kk = 0; kk < BK; kk++) {
            const float4 wq = *(const float4*)(Wt + kk * WTS + tx * 4);  // conflict-free
            unsigned long long wd0, wd1, wd2, wd3;
            DUP2(wd0, wq.x); DUP2(wd1, wq.y); DUP2(wd2, wq.z); DUP2(wd3, wq.w);

            const float* ab = As + kk * AST + ty * 16;    // warp-uniform -> broadcast
            const ulonglong2 a01 = *(const ulonglong2*)(ab);
            const ulonglong2 a23 = *(const ulonglong2*)(ab + 4);
            const ulonglong2 a45 = *(const ulonglong2*)(ab + 8);
            const ulonglong2 a67 = *(const ulonglong2*)(ab + 12);

#pragma unroll
            for (int n = 0; n < 4; n++) {
                const unsigned long long wv = (n == 0) ? wd0 : (n == 1) ? wd1
                                            : (n == 2) ? wd2 : wd3;
                FFMA2(acc[0][n], a01.x, wv);
                FFMA2(acc[1][n], a01.y, wv);
                FFMA2(acc[2][n], a23.x, wv);
                FFMA2(acc[3][n], a23.y, wv);
                FFMA2(acc[4][n], a45.x, wv);
                FFMA2(acc[5][n], a45.y, wv);
                FFMA2(acc[6][n], a67.x, wv);
                FFMA2(acc[7][n], a67.y, wv);
            }
        }
        __syncthreads();
    }

    const float4 bb = *(const float4*)(b + tx * 4);
#pragma unroll
    for (int p = 0; p < 8; p++) {
        const int row0 = m0g + ty * 16 + 2 * p;
        const float2 f0 = *(const float2*)&acc[p][0];
        const float2 f1 = *(const float2*)&acc[p][1];
        const float2 f2 = *(const float2*)&acc[p][2];
        const float2 f3 = *(const float2*)&acc[p][3];
        if (row0 < NN) {
            float4 o;
            o.x = (f0.x + bb.x) * scale;
            o.y = (f1.x + bb.y) * scale;
            o.z = (f2.x + bb.z) * scale;
            o.w = (f3.x + bb.w) * scale;
            *(float4*)(Out + (size_t)row0 * rstride + tx * 4) = o;
        }
        if (row0 + 1 < NN) {
            float4 o;
            o.x = (f0.y + bb.x) * scale;
            o.y = (f1.y + bb.y) * scale;
            o.z = (f2.y + bb.z) * scale;
            o.w = (f3.y + bb.w) * scale;
            *(float4*)(Out + (size_t)(row0 + 1) * rstride + tx * 4) = o;
        }
    }
}

// ---------------- aggregation: one warp per dst node --------------------------
__global__ void aggregate_kernel(float* __restrict__ out)
{
    if (blockIdx.x == 0 && threadIdx.x == 0) atomicExch(&g_scandone, 0);

    const int warp = (blockIdx.x * blockDim.x + threadIdx.x) >> 5;
    if (warp >= NN) return;
    const int lane = threadIdx.x & 31;
    const unsigned lane4 = lane * 4;
    const int n = warp;

    const int beg = g_offs[n];
    const int end = g_offs[n + 1];

    const unsigned fo = ((unsigned)n << 7) + lane4;
    const float4 fd = *(const float4*)(g_fdst + fo);

    float nx = 0.f, ny = 0.f, nz = 0.f, nw = 0.f;
    float dx = 0.f, dy = 0.f, dz = 0.f, dw = 0.f;

#define EDGE_STEP(fs, fvv)                                                        \
    do {                                                                          \
        float a_, e_;                                                             \
        a_ = fs.x + fd.x; e_ = ex2f(fmaxf(a_, NEG * a_)); dx += e_; nx = fmaf(fvv.x, e_, nx); \
        a_ = fs.y + fd.y; e_ = ex2f(fmaxf(a_, NEG * a_)); dy += e_; ny = fmaf(fvv.y, e_, ny); \
        a_ = fs.z + fd.z; e_ = ex2f(fmaxf(a_, NEG * a_)); dz += e_; nz = fmaf(fvv.z, e_, nz); \
        a_ = fs.w + fd.w; e_ = ex2f(fmaxf(a_, NEG * a_)); dw += e_; nw = fmaf(fvv.w, e_, nw); \
    } while (0)

    for (int base = beg; base < end; base += 32) {
        const int rem = end - base;
        const int m = rem < 32 ? rem : 32;
        const int s_l = (lane < m) ? __ldg(&g_ssrc[base + lane]) : 0;
        int t = 0;
        for (; t + 2 <= m; t += 2) {
            const unsigned o0 = ((unsigned)__shfl_sync(0xffffffffu, s_l, t)     << 8) + lane4;
            const unsigned o1 = ((unsigned)__shfl_sync(0xffffffffu, s_l, t + 1) << 8) + lane4;
            const float4 fs0 = *(const float4*)(g_fsv + o0);
            const float4 fv0 = *(const float4*)(g_fsv + o0 + 128);
            const float4 fs1 = *(const float4*)(g_fsv + o1);
            const float4 fv1 = *(const float4*)(g_fsv + o1 + 128);
            EDGE_STEP(fs0, fv0);
            EDGE_STEP(fs1, fv1);
        }
        if (t < m) {
            const unsigned o0 = ((unsigned)__shfl_sync(0xffffffffu, s_l, t) << 8) + lane4;
            const float4 fs0 = *(const float4*)(g_fsv + o0);
            const float4 fv0 = *(const float4*)(g_fsv + o0 + 128);
            EDGE_STEP(fs0, fv0);
        }
    }

    float4 o;
    o.x = dx > 0.f ? nx / dx : 0.f;
    o.y = dy > 0.f ? ny / dy : 0.f;
    o.z = dz > 0.f ? nz / dz : 0.f;
    o.w = dw > 0.f ? nw / dw : 0.f;
    *(float4*)(out + fo) = o;
}

// ---------------- launch -------------------------------------------------------
extern "C" void kernel_launch(void* const* d_in, const int* in_sizes, int n_in,
                              void* d_out, int out_size)
{
    const float* feat = (const float*)d_in[0];
    const float* Wsrc = (const float*)d_in[1];
    const float* bsrc = (const float*)d_in[2];
    const float* Wdst = (const float*)d_in[3];
    const float* bdst = (const float*)d_in[4];
    const float* Wv   = (const float*)d_in[5];
    const float* bv   = (const float*)d_in[6];
    const int*   src  = (const int*)d_in[7];
    const int*   dst  = (const int*)d_in[8];
    float* out = (float*)d_out;

    cudaFuncSetAttribute(gemm_csr_kernel,
                         cudaFuncAttributeMaxDynamicSharedMemorySize, SMEM_BYTES);

    gemm_csr_kernel<<<GRID1, 256, SMEM_BYTES>>>(
        feat, Wsrc, bsrc, Wdst, bdst, Wv, bv, src, dst);

    aggregate_kernel<<<(NN * 32 + 255) / 256, 256>>>(out);
}

// round 8
// speedup vs baseline: 1.4550x; 1.0155x over previous
#include <cuda_runtime.h>
#include <cstdint>

#define NN 50000
#define EE 800000
#define INF 128
#define HD  128
#define NEG 0.2f
#define LOG2E 1.44269504088896340736f

#define BM 128
#define NTILE ((NN + BM - 1) / BM)    // 391
#define HBLK 148                       // histogram blocks (bids 0..147)
#define SCANB HBLK                     // scan block (bid 148)
#define SCAT0 (SCANB + 1)              // scatter blocks (bids 149..295)
#define SBLK 147
#define GEMM0 (SCAT0 + SBLK)           // 296
#define NGEMM (3 * NTILE)              // 1173 (one matrix-tile per block)
#define GRID1 (GEMM0 + NGEMM)

// ---------------- scratch ------------------------------------------------------
__device__ float g_fsv [(size_t)NN * 256];  // [node][0:128)=f_src*LOG2E, [128:256)=f_v
__device__ float g_fdst[(size_t)NN * HD];   // pre-scaled by LOG2E
__device__ int   g_deg [NN];                // zeroed by scan pass each launch
__device__ int   g_offs[NN + 1];
__device__ int   g_cur [NN];
__device__ int   g_ssrc[EE];
__device__ int   g_histdone;
__device__ int   g_scandone;

__device__ __forceinline__ float ex2f(float x) {
    float r;
    asm("ex2.approx.f32 %0, %1;" : "=f"(r) : "f"(x));
    return r;
}

// pack two f32 into bf16x2 (lo -> low half, hi -> high half)
__device__ __forceinline__ uint32_t pack_bf16x2(float lo, float hi) {
    uint32_t u;
    asm("cvt.rn.bf16x2.f32 %0, %1, %2;" : "=r"(u) : "f"(hi), "f"(lo));
    return u;
}
__device__ __forceinline__ float bflo(uint32_t u) { return __uint_as_float(u << 16); }
__device__ __forceinline__ float bfhi(uint32_t u) { return __uint_as_float(u & 0xffff0000u); }

// split float2 -> (hi bf16x2, residual bf16x2)
__device__ __forceinline__ void split2(float2 v, uint32_t& h, uint32_t& l) {
    h = pack_bf16x2(v.x, v.y);
    l = pack_bf16x2(v.x - bflo(h), v.y - bfhi(h));
}

#define MMA16816(d, a, b0, b1)                                                    \
    asm volatile("mma.sync.aligned.m16n8k16.row.col.f32.bf16.bf16.f32 "           \
                 "{%0,%1,%2,%3}, {%4,%5,%6,%7}, {%8,%9}, {%0,%1,%2,%3};"          \
                 : "+f"((d)[0]), "+f"((d)[1]), "+f"((d)[2]), "+f"((d)[3])         \
                 : "r"((a)[0]), "r"((a)[1]), "r"((a)[2]), "r"((a)[3]),            \
                   "r"(b0), "r"(b1))

// ---------------- mega-kernel: hist+scan+scatter (wave 1) + HMMA GEMM ----------
__global__ void __launch_bounds__(256, 2)
gemm_csr_kernel(const float* __restrict__ feat,
                const float* __restrict__ Wsrc, const float* __restrict__ bsrc,
                const float* __restrict__ Wdst, const float* __restrict__ bdst,
                const float* __restrict__ Wv,   const float* __restrict__ bv,
                const int* __restrict__ src, const int* __restrict__ dst)
{
    const int bid = blockIdx.x;
    const int tid = threadIdx.x;

    // ---------- role: histogram ----------
    if (bid < HBLK) {
        for (int i = bid * 256 + tid; i < EE; i += HBLK * 256)
            atomicAdd(&g_deg[dst[i]], 1);
        __threadfence();
        __syncthreads();
        if (tid == 0) atomicAdd(&g_histdone, 1);
        return;
    }

    // ---------- role: scan (single block; spins until hist done) ----------
    if (bid == SCANB) {
        if (tid == 0) {
            while (atomicAdd(&g_histdone, 0) < HBLK) __nanosleep(128);
            atomicExch(&g_histdone, 0);
        }
        __syncthreads();
        __threadfence();

        const int CH = (NN + 255) / 256;
        const int beg = tid * CH;
        const int end = (beg + CH < NN) ? beg + CH : NN;

        int s = 0;
#pragma unroll 4
        for (int i = beg; i < end; i++) s += __ldcg(&g_deg[i]);

        __shared__ int wsum[8];
        const int lane = tid & 31, wid = tid >> 5;
        int inc = s;
#pragma unroll
        for (int o = 1; o < 32; o <<= 1) {
            const int u = __shfl_up_sync(0xffffffffu, inc, o);
            if (lane >= o) inc += u;
        }
        if (lane == 31) wsum[wid] = inc;
        __syncthreads();
        if (wid == 0 && lane < 8) {
            int w = wsum[lane];
#pragma unroll
            for (int o = 1; o < 8; o <<= 1) {
                const int u = __shfl_up_sync(0x000000ffu, w, o);
                if (lane >= o) w += u;
            }
            wsum[lane] = w;
        }
        __syncthreads();
        int run = (inc - s) + (wid ? wsum[wid - 1] : 0);

#pragma unroll 4
        for (int i = beg; i < end; i++) {
            const int d = __ldcg(&g_deg[i]);
            __stcg(&g_deg[i], 0);
            g_offs[i] = run;
            g_cur[i]  = run;
            run += d;
        }
        if (tid == 255) g_offs[NN] = run;

        __threadfence();
        __syncthreads();
        if (tid == 0) atomicExch(&g_scandone, 1);
        return;
    }

    // ---------- role: scatter (spins until scan done) ----------
    if (bid < GEMM0) {
        if (tid == 0)
            while (atomicAdd(&g_scandone, 0) == 0) __nanosleep(128);
        __syncthreads();
        for (int i = (bid - SCAT0) * 256 + tid; i < EE; i += SBLK * 256) {
            const int d = dst[i];
            const int p = atomicAdd(&g_cur[d], 1);
            g_ssrc[p] = src[i];
        }
        return;
    }

    // ---------- role: HMMA GEMM (bf16-split, no smem) ----------
    // One 128-row tile of one matrix per block; warp w owns rows [16w,16w+16).
    // D = ah*wh + ah*wl + al*wh in f32 HMMA accumulation (al*wl dropped, ~4e-6).
    const int bx   = bid - GEMM0;
    const int mat  = bx / NTILE;
    const int tile = bx % NTILE;
    const int m0g  = tile * BM;

    const float* W;
    const float* b;
    float* Out;
    float scale;
    unsigned rstride;
    if (mat == 0)      { W = Wsrc; b = bsrc; Out = g_fsv;       scale = LOG2E; rstride = 256; }
    else if (mat == 1) { W = Wdst; b = bdst; Out = g_fdst;      scale = LOG2E; rstride = 128; }
    else               { W = Wv;   b = bv;   Out = g_fsv + 128; scale = 1.0f;  rstride = 256; }

    const int wm   = tid >> 5;          // warp's m-group
    const int lane = tid & 31;
    const int gi   = lane >> 2;         // group id 0..7
    const int tg   = lane & 3;          // thread-in-group

    const int r0 = m0g + wm * 16 + gi;  // fragment row (lo)
    const int r1 = r0 + 8;              // fragment row (hi)
    const bool v0 = (r0 < NN);
    const bool v1 = (r1 < NN);
    const int kcol = tg * 2;

    float acc[16][4];
#pragma unroll
    for (int ng = 0; ng < 16; ng++)
#pragma unroll
        for (int i = 0; i < 4; i++) acc[ng][i] = 0.f;

    const float* a0p = feat + (size_t)r0 * INF + kcol;
    const float* a1p = feat + (size_t)r1 * INF + kcol;
    const float* wbp = W + (size_t)(gi)*INF + kcol;

    for (int kg = 0; kg < 8; kg++) {
        const int kb = kg * 16;
        // ---- A fragments (hi/lo split) ----
        float2 fa0 = v0 ? *(const float2*)(a0p + kb)     : make_float2(0.f, 0.f);
        float2 fa1 = v1 ? *(const float2*)(a1p + kb)     : make_float2(0.f, 0.f);
        float2 fa2 = v0 ? *(const float2*)(a0p + kb + 8) : make_float2(0.f, 0.f);
        float2 fa3 = v1 ? *(const float2*)(a1p + kb + 8) : make_float2(0.f, 0.f);
        uint32_t ah[4], al[4];
        split2(fa0, ah[0], al[0]);
        split2(fa1, ah[1], al[1]);
        split2(fa2, ah[2], al[2]);
        split2(fa3, ah[3], al[3]);

#pragma unroll
        for (int ng = 0; ng < 16; ng++) {
            const float* wp = wbp + (size_t)ng * (8 * INF) + kb;
            const float2 w0 = *(const float2*)(wp);
            const float2 w1 = *(const float2*)(wp + 8);
            uint32_t bh0, bl0, bh1, bl1;
            split2(w0, bh0, bl0);
            split2(w1, bh1, bl1);
            MMA16816(acc[ng], ah, bh0, bh1);
            MMA16816(acc[ng], ah, bl0, bl1);
            MMA16816(acc[ng], al, bh0, bh1);
        }
    }

    // ---- epilogue: bias + scale, direct float2 stores ----
#pragma unroll
    for (int ng = 0; ng < 16; ng++) {
        const int c = ng * 8 + kcol;
        const float2 bb = *(const float2*)(b + c);
        if (v0) {
            float2 o;
            o.x = (acc[ng][0] + bb.x) * scale;
            o.y = (acc[ng][1] + bb.y) * scale;
            *(float2*)(Out + (size_t)r0 * rstride + c) = o;
        }
        if (v1) {
            float2 o;
            o.x = (acc[ng][2] + bb.x) * scale;
            o.y = (acc[ng][3] + bb.y) * scale;
            *(float2*)(Out + (size_t)r1 * rstride + c) = o;
        }
    }
}

// ---------------- aggregation: one warp per dst node --------------------------
__global__ void aggregate_kernel(float* __restrict__ out)
{
    if (blockIdx.x == 0 && threadIdx.x == 0) atomicExch(&g_scandone, 0);

    const int warp = (blockIdx.x * blockDim.x + threadIdx.x) >> 5;
    if (warp >= NN) return;
    const int lane = threadIdx.x & 31;
    const unsigned lane4 = lane * 4;
    const int n = warp;

    const int beg = g_offs[n];
    const int end = g_offs[n + 1];

    const unsigned fo = ((unsigned)n << 7) + lane4;
    const float4 fd = *(const float4*)(g_fdst + fo);

    float nx = 0.f, ny = 0.f, nz = 0.f, nw = 0.f;
    float dx = 0.f, dy = 0.f, dz = 0.f, dw = 0.f;

#define EDGE_STEP(fs, fvv)                                                        \
    do {                                                                          \
        float a_, e_;                                                             \
        a_ = fs.x + fd.x; e_ = ex2f(fmaxf(a_, NEG * a_)); dx += e_; nx = fmaf(fvv.x, e_, nx); \
        a_ = fs.y + fd.y; e_ = ex2f(fmaxf(a_, NEG * a_)); dy += e_; ny = fmaf(fvv.y, e_, ny); \
        a_ = fs.z + fd.z; e_ = ex2f(fmaxf(a_, NEG * a_)); dz += e_; nz = fmaf(fvv.z, e_, nz); \
        a_ = fs.w + fd.w; e_ = ex2f(fmaxf(a_, NEG * a_)); dw += e_; nw = fmaf(fvv.w, e_, nw); \
    } while (0)

    for (int base = beg; base < end; base += 32) {
        const int rem = end - base;
        const int m = rem < 32 ? rem : 32;
        const int s_l = (lane < m) ? __ldg(&g_ssrc[base + lane]) : 0;
        int t = 0;
        for (; t + 2 <= m; t += 2) {
            const unsigned o0 = ((unsigned)__shfl_sync(0xffffffffu, s_l, t)     << 8) + lane4;
            const unsigned o1 = ((unsigned)__shfl_sync(0xffffffffu, s_l, t + 1) << 8) + lane4;
            const float4 fs0 = *(const float4*)(g_fsv + o0);
            const float4 fv0 = *(const float4*)(g_fsv + o0 + 128);
            const float4 fs1 = *(const float4*)(g_fsv + o1);
            const float4 fv1 = *(const float4*)(g_fsv + o1 + 128);
            EDGE_STEP(fs0, fv0);
            EDGE_STEP(fs1, fv1);
        }
        if (t < m) {
            const unsigned o0 = ((unsigned)__shfl_sync(0xffffffffu, s_l, t) << 8) + lane4;
            const float4 fs0 = *(const float4*)(g_fsv + o0);
            const float4 fv0 = *(const float4*)(g_fsv + o0 + 128);
            EDGE_STEP(fs0, fv0);
        }
    }

    float4 o;
    o.x = dx > 0.f ? nx / dx : 0.f;
    o.y = dy > 0.f ? ny / dy : 0.f;
    o.z = dz > 0.f ? nz / dz : 0.f;
    o.w = dw > 0.f ? nw / dw : 0.f;
    *(float4*)(out + fo) = o;
}

// ---------------- launch -------------------------------------------------------
extern "C" void kernel_launch(void* const* d_in, const int* in_sizes, int n_in,
                              void* d_out, int out_size)
{
    const float* feat = (const float*)d_in[0];
    const float* Wsrc = (const float*)d_in[1];
    const float* bsrc = (const float*)d_in[2];
    const float* Wdst = (const float*)d_in[3];
    const float* bdst = (const float*)d_in[4];
    const float* Wv   = (const float*)d_in[5];
    const float* bv   = (const float*)d_in[6];
    const int*   src  = (const int*)d_in[7];
    const int*   dst  = (const int*)d_in[8];
    float* out = (float*)d_out;

    gemm_csr_kernel<<<GRID1, 256>>>(
        feat, Wsrc, bsrc, Wdst, bdst, Wv, bv, src, dst);

    aggregate_kernel<<<(NN * 32 + 255) / 256, 256>>>(out);
}